// round 12
// baseline (speedup 1.0000x reference)
#include <cuda_runtime.h>
#include <cuda_bf16.h>
#include <cstdint>

#define DI __device__ __forceinline__

// bitsandbytes FP4 codebook (sign = bit 3)
__constant__ float FP4_TAB[16] = {
     0.0f,  0.0052083333f,  0.6666667f,  1.0f,  0.3333333f,  0.5f,  0.1666667f,  0.25f,
    -0.0f, -0.0052083333f, -0.6666667f, -1.0f, -0.3333333f, -0.5f, -0.1666667f, -0.25f};

#define B_ 16384L
#define I_ 2048L
#define H_ 4096L
#define O_ 2048L

// scratch (alloc-free rule: __device__ globals)
__device__ float g_Xf[B_ * I_];           // exact bf16 values in f32 (layer-1 inputs)
__device__ float g_W1f[H_ * I_];
__device__ __nv_bfloat16 g_H1b[B_ * H_];  // layer-1 output, bf16 (exact)
__device__ __nv_bfloat16 g_W2b[H_ * H_];  // layer-2 weights, bf16
__device__ __nv_bfloat16 g_H2b[B_ * H_];  // layer-2 output, bf16
__device__ __nv_bfloat16 g_W3b[O_ * H_];  // layer-3 weights, bf16

DI float bf16v(float x) { return __bfloat162float(__float2bfloat16(x)); }

// packed dual-FP32 FMA (Blackwell FFMA2): per-lane IEEE RN fma.
DI void fma2(uint64_t& d, uint64_t a, uint64_t b) {
    asm("fma.rn.f32x2 %0, %1, %2, %3;" : "=l"(d) : "l"(a), "l"(b), "l"(d));
}
DI uint64_t pack2(float lo, float hi) {
    uint64_t r;
    asm("mov.b64 %0, {%1, %2};" : "=l"(r) : "f"(lo), "f"(hi));
    return r;
}
DI void unpack2(float& lo, float& hi, uint64_t v) {
    asm("mov.b64 {%0, %1}, %2;" : "=f"(lo), "=f"(hi) : "l"(v));
}

DI uint32_t s2u(const void* p) { return (uint32_t)__cvta_generic_to_shared(p); }
DI void cp16(uint32_t s, const void* g) {
    asm volatile("cp.async.cg.shared.global [%0], [%1], 16;\n" :: "r"(s), "l"(g) : "memory");
}
DI void cp_commit() { asm volatile("cp.async.commit_group;\n" ::: "memory"); }
template <int N>
DI void cp_wait() { asm volatile("cp.async.wait_group %0;\n" :: "n"(N) : "memory"); }
DI uint32_t lds32u(const __nv_bfloat16* p) { return *reinterpret_cast<const uint32_t*>(p); }
DI void mma16816(float* c, const uint32_t* a, const uint32_t* b) {
    asm volatile(
        "mma.sync.aligned.m16n8k16.row.col.f32.bf16.bf16.f32 "
        "{%0,%1,%2,%3}, {%4,%5,%6,%7}, {%8,%9}, {%0,%1,%2,%3};\n"
        : "+f"(c[0]), "+f"(c[1]), "+f"(c[2]), "+f"(c[3])
        : "r"(a[0]), "r"(a[1]), "r"(a[2]), "r"(a[3]), "r"(b[0]), "r"(b[1]));
}

// ---------------------------------------------------------------------------
// Elementwise prep
// ---------------------------------------------------------------------------

__global__ void cast_kernel(const float* __restrict__ x, float* __restrict__ y) {
    long i4 = blockIdx.x * (long)blockDim.x + threadIdx.x;
    float4 v = reinterpret_cast<const float4*>(x)[i4];
    float4 o;
    o.x = bf16v(v.x); o.y = bf16v(v.y); o.z = bf16v(v.z); o.w = bf16v(v.w);
    reinterpret_cast<float4*>(y)[i4] = o;
}

__global__ void dequant_kernel_f32(const int* __restrict__ codes,
                                   const float* __restrict__ absmax,
                                   float* __restrict__ w) {
    long i4 = blockIdx.x * (long)blockDim.x + threadIdx.x;
    int4 c = reinterpret_cast<const int4*>(codes)[i4];
    float am = __ldg(&absmax[(i4 * 4) >> 6]);
    float4 o;
    o.x = bf16v(FP4_TAB[c.x & 15] * am);
    o.y = bf16v(FP4_TAB[c.y & 15] * am);
    o.z = bf16v(FP4_TAB[c.z & 15] * am);
    o.w = bf16v(FP4_TAB[c.w & 15] * am);
    reinterpret_cast<float4*>(w)[i4] = o;
}

__global__ void dequant_kernel_bf16(const int* __restrict__ codes,
                                    const float* __restrict__ absmax,
                                    __nv_bfloat16* __restrict__ w) {
    long i4 = blockIdx.x * (long)blockDim.x + threadIdx.x;
    int4 c = reinterpret_cast<const int4*>(codes)[i4];
    float am = __ldg(&absmax[(i4 * 4) >> 6]);
    __nv_bfloat162 p0 = __floats2bfloat162_rn(FP4_TAB[c.x & 15] * am, FP4_TAB[c.y & 15] * am);
    __nv_bfloat162 p1 = __floats2bfloat162_rn(FP4_TAB[c.z & 15] * am, FP4_TAB[c.w & 15] * am);
    reinterpret_cast<__nv_bfloat162*>(w)[i4 * 2 + 0] = p0;
    reinterpret_cast<__nv_bfloat162*>(w)[i4 * 2 + 1] = p1;
}

// ---------------------------------------------------------------------------
// Layer 1: order-exact SGEMM on the FFMA2 pipe. A is stored DUPLICATED in smem
// with an interleaved chunk layout so the mainloop has zero pack-MOVs and
// conflict-free LDS.128s: per warp-k = 4 LDS.128 (A) + 2 LDS.128 (B) + 32 FFMA2.
// Per-element math is bit-identical to R8/R10 (one sequential IEEE-FMA chain
// over ascending k).
//
// A-dup layout per k-row (256 floats): two 64-row halves; within a half,
// 16B chunk (q*8 + lr) holds dup pairs for rows (lr*8 + 2q, lr*8 + 2q + 1).
// Lane (lr) mainloop reads chunks q=0..3 at byte offset lr*16 + q*128 —
// all 8 lr hit distinct mod-128 positions -> conflict-free.
// ---------------------------------------------------------------------------

__global__ void __launch_bounds__(256)
sgemm_f32x2_l1(const float* __restrict__ A,   // [M,K] f32 (bf16 values)
               const float* __restrict__ W,   // [N,K] f32 (bf16 values)
               const float* __restrict__ bias,
               __nv_bfloat16* __restrict__ C,
               int M, int N, int K) {
    constexpr int BM = 128, BN = 128, BK = 16;
    constexpr int LWA = 264;   // floats per k-row of A-dup (256 used + pad)
    constexpr int LWB = 132;
    __shared__ __align__(16) float sA[BK][LWA];
    __shared__ __align__(16) float sB[BK][LWB];

    const int tid  = threadIdx.x;
    const int lane = tid & 31;
    const int warp = tid >> 5;
    const int wm = (warp & 1) * 64;
    const int wn = (warp >> 1) * 32;
    const int lr = lane >> 2;
    const int lc = lane & 3;
    const int m0 = blockIdx.y * BM;
    const int n0 = blockIdx.x * BN;

    // gmem->smem staging: thread owns A-row sr / W-row sr, k-half sc
    const int sr = tid >> 1;            // 0..127
    const int sc = (tid & 1) * 8;       // 0 or 8

    // A-dup staging target (float offset within a k-row) for row sr:
    const int half = sr >> 6;           // 0/1
    const int hh   = sr & 63;
    const int lrp  = hh >> 3;
    const int ii   = hh & 7;
    const int aoff = half * 128 + ((ii >> 1) * 8 + lrp) * 4 + (ii & 1) * 2;

    const float* gA = A + (size_t)(m0 + sr) * K + sc;
    const float* gW = W + (size_t)(n0 + sr) * K + sc;

    uint64_t acc[8][4];
#pragma unroll
    for (int i = 0; i < 8; i++)
#pragma unroll
        for (int j = 0; j < 4; j++) acc[i][j] = 0ull;

    float ra[8], rb[8];
    auto gload = [&]() {
        *reinterpret_cast<float4*>(ra)     = *reinterpret_cast<const float4*>(gA);
        *reinterpret_cast<float4*>(ra + 4) = *reinterpret_cast<const float4*>(gA + 4);
        *reinterpret_cast<float4*>(rb)     = *reinterpret_cast<const float4*>(gW);
        *reinterpret_cast<float4*>(rb + 4) = *reinterpret_cast<const float4*>(gW + 4);
    };
    auto sstore = [&]() {
#pragma unroll
        for (int t = 0; t < 8; t++) {
            *reinterpret_cast<uint64_t*>(&sA[sc + t][aoff]) = pack2(ra[t], ra[t]);
            sB[sc + t][sr] = rb[t];
        }
    };

    const int KT = K / BK;
    gload();
    for (int kt = 0; kt < KT; ++kt) {
        sstore();
        __syncthreads();
        if (kt + 1 < KT) { gA += BK; gW += BK; gload(); }

        const int abase = wm * 2 + lr * 4;   // float offset of lane's chunk q=0
#pragma unroll
        for (int k = 0; k < BK; k++) {       // ascending k — preserves chain order
            const float* ab = &sA[k][abase];
            uint64_t ad[8];
            *reinterpret_cast<ulonglong2*>(&ad[0]) = *reinterpret_cast<const ulonglong2*>(ab);
            *reinterpret_cast<ulonglong2*>(&ad[2]) = *reinterpret_cast<const ulonglong2*>(ab + 32);
            *reinterpret_cast<ulonglong2*>(&ad[4]) = *reinterpret_cast<const ulonglong2*>(ab + 64);
            *reinterpret_cast<ulonglong2*>(&ad[6]) = *reinterpret_cast<const ulonglong2*>(ab + 96);
            uint64_t bp[4];
            const uint64_t* bq = reinterpret_cast<const uint64_t*>(&sB[k][wn + lc * 8]);
            bp[0] = bq[0]; bp[1] = bq[1]; bp[2] = bq[2]; bp[3] = bq[3];
#pragma unroll
            for (int i = 0; i < 8; i++)
#pragma unroll
                for (int j = 0; j < 4; j++)
                    fma2(acc[i][j], ad[i], bp[j]);
        }
        __syncthreads();
    }

    // Epilogue — reference rounding: bf16(dot), + bf16(bias), bf16 round, relu.
    float bb[8];
#pragma unroll
    for (int j = 0; j < 8; j++) bb[j] = bf16v(bias[n0 + wn + lc * 8 + j]);

#pragma unroll
    for (int i = 0; i < 8; i++) {
        const int row = m0 + wm + lr * 8 + i;
        __nv_bfloat16* cp = C + (size_t)row * N + n0 + wn + lc * 8;
#pragma unroll
        for (int j = 0; j < 4; j++) {
            float v0, v1;
            unpack2(v0, v1, acc[i][j]);
            v0 = fmaxf(bf16v(bf16v(v0) + bb[2 * j]), 0.f);
            v1 = fmaxf(bf16v(bf16v(v1) + bb[2 * j + 1]), 0.f);
            reinterpret_cast<__nv_bfloat162*>(cp)[j] = __floats2bfloat162_rn(v0, v1);
        }
    }
}

// ---------------------------------------------------------------------------
// Layers 2-3: HMMA bf16 GEMM, 3-stage cp.async pipeline, ONE sync per k-tile.
// BK=16 (same ascending-k16 mma order as before -> bit-identical outputs).
// ---------------------------------------------------------------------------

template <bool RELU, bool OUT_F32>
__global__ void __launch_bounds__(256)
gemm_hmma(const __nv_bfloat16* __restrict__ A,
          const __nv_bfloat16* __restrict__ W,
          const float* __restrict__ bias,
          void* __restrict__ Cv,
          int M, int N, int K) {
    constexpr int BM = 128, BN = 128, BK = 16, LDS = BK + 8, STG = 3;

    __shared__ __align__(16) __nv_bfloat16 sA[STG][BM * LDS];  // 3*128*24*2 = 18.4KB
    __shared__ __align__(16) __nv_bfloat16 sB[STG][BN * LDS];

    const int tid = threadIdx.x;
    const int lane = tid & 31;
    const int warp = tid >> 5;
    const int wm = (warp & 1) * 64;
    const int wn = (warp >> 1) * 32;
    const int m0 = blockIdx.y * BM;
    const int n0 = blockIdx.x * BN;

    const int gid = lane >> 2;
    const int tg  = lane & 3;
    const int kfr = tg * 2;

    // staging: 128 rows x 16 bf16 = 256 x 16B chunks per matrix; 1 per thread
    const int r_ld = tid >> 1;          // 0..127
    const int c_ld = (tid & 1) * 8;     // 0 or 8

    float acc[4][4][4];
#pragma unroll
    for (int i = 0; i < 4; i++)
#pragma unroll
        for (int j = 0; j < 4; j++)
#pragma unroll
            for (int q = 0; q < 4; q++) acc[i][j][q] = 0.f;

    auto load_stage = [&](int s, int kt) {
        const int k0 = kt * BK;
        cp16(s2u(&sA[s][r_ld * LDS + c_ld]), A + (size_t)(m0 + r_ld) * K + k0 + c_ld);
        cp16(s2u(&sB[s][r_ld * LDS + c_ld]), W + (size_t)(n0 + r_ld) * K + k0 + c_ld);
    };

    auto compute_stage = [&](int s) {
        const __nv_bfloat16* pA = sA[s];
        const __nv_bfloat16* pB = sB[s];
        uint32_t a[4][4], b[4][2];
#pragma unroll
        for (int mt = 0; mt < 4; mt++) {
            const int r = wm + mt * 16 + gid;
            a[mt][0] = lds32u(&pA[(r    ) * LDS + kfr    ]);
            a[mt][1] = lds32u(&pA[(r + 8) * LDS + kfr    ]);
            a[mt][2] = lds32u(&pA[(r    ) * LDS + kfr + 8]);
            a[mt][3] = lds32u(&pA[(r + 8) * LDS + kfr + 8]);
        }
#pragma unroll
        for (int nt = 0; nt < 4; nt++) {
            const int n = wn + nt * 8 + gid;
            b[nt][0] = lds32u(&pB[n * LDS + kfr    ]);
            b[nt][1] = lds32u(&pB[n * LDS + kfr + 8]);
        }
#pragma unroll
        for (int mt = 0; mt < 4; mt++)
#pragma unroll
            for (int nt = 0; nt < 4; nt++)
                mma16816(acc[mt][nt], a[mt], b[nt]);
    };

    const int KT = K / BK;
    load_stage(0, 0); cp_commit();
    load_stage(1, 1); cp_commit();     // KT >= 2 always here (K >= 2048)

    for (int kt = 0; kt < KT; ++kt) {
        cp_wait<1>();                  // group kt has landed (empty groups count)
        __syncthreads();               // visible to all; prior compute finished
        if (kt + 2 < KT) load_stage((kt + 2) % STG, kt + 2);
        cp_commit();                   // exactly one group per iteration
        compute_stage(kt % STG);
    }

    // Epilogue — reference rounding: bf16(dot) + bf16(bias) -> bf16 (+relu).
    __nv_bfloat16* Cb = (__nv_bfloat16*)Cv;
    float* Cf = (float*)Cv;
#pragma unroll
    for (int mt = 0; mt < 4; mt++) {
        const int rr = m0 + wm + mt * 16 + gid;
#pragma unroll
        for (int nt = 0; nt < 4; nt++) {
            const int cc = n0 + wn + nt * 8 + tg * 2;
            const float b0 = bf16v(bias[cc]);
            const float b1 = bf16v(bias[cc + 1]);
            const float* cr = acc[mt][nt];

            float v0 = bf16v(bf16v(cr[0]) + b0);
            float v1 = bf16v(bf16v(cr[1]) + b1);
            float v2 = bf16v(bf16v(cr[2]) + b0);
            float v3 = bf16v(bf16v(cr[3]) + b1);
            if (RELU) {
                v0 = fmaxf(v0, 0.f); v1 = fmaxf(v1, 0.f);
                v2 = fmaxf(v2, 0.f); v3 = fmaxf(v3, 0.f);
            }
            if (OUT_F32) {
                *reinterpret_cast<float2*>(&Cf[(size_t)rr * N + cc]) = make_float2(v0, v1);
                *reinterpret_cast<float2*>(&Cf[(size_t)(rr + 8) * N + cc]) = make_float2(v2, v3);
            } else {
                *reinterpret_cast<__nv_bfloat162*>(&Cb[(size_t)rr * N + cc]) =
                    __floats2bfloat162_rn(v0, v1);
                *reinterpret_cast<__nv_bfloat162*>(&Cb[(size_t)(rr + 8) * N + cc]) =
                    __floats2bfloat162_rn(v2, v3);
            }
        }
    }
}

// ---------------------------------------------------------------------------

extern "C" void kernel_launch(void* const* d_in, const int* in_sizes, int n_in,
                              void* d_out, int out_size) {
    // Resolve inputs by element count (robust to metadata ordering).
    const float* x = nullptr;
    const int *codes1 = nullptr, *codes2 = nullptr, *codes3 = nullptr;
    const float *absmax1 = nullptr, *absmax2 = nullptr, *absmax3 = nullptr;
    const float *bias1 = nullptr, *bias2 = nullptr, *bias3 = nullptr;

    for (int i = 0; i < n_in; i++) {
        const long sz = in_sizes[i];
        const void* p = d_in[i];
        if (sz == B_ * I_) x = (const float*)p;
        else if (sz == H_ * H_) codes2 = (const int*)p;
        else if (sz == H_ * I_) { if (!codes1) codes1 = (const int*)p; else codes3 = (const int*)p; }
        else if (sz == (H_ * H_) / 64) absmax2 = (const float*)p;
        else if (sz == (H_ * I_) / 64) { if (!absmax1) absmax1 = (const float*)p; else absmax3 = (const float*)p; }
        else if (sz == H_) { if (!bias1) bias1 = (const float*)p; else bias2 = (const float*)p; }
        else if (sz == O_) bias3 = (const float*)p;
    }

    float *Xf, *W1;
    __nv_bfloat16 *H1b, *W2b, *H2b, *W3b;
    cudaGetSymbolAddress((void**)&Xf, g_Xf);
    cudaGetSymbolAddress((void**)&W1, g_W1f);
    cudaGetSymbolAddress((void**)&H1b, g_H1b);
    cudaGetSymbolAddress((void**)&W2b, g_W2b);
    cudaGetSymbolAddress((void**)&H2b, g_H2b);
    cudaGetSymbolAddress((void**)&W3b, g_W3b);

    // elementwise prep
    cast_kernel<<<(unsigned)((B_ * I_) / 4 / 256), 256>>>(x, Xf);
    dequant_kernel_f32<<<(unsigned)((H_ * I_) / 4 / 256), 256>>>(codes1, absmax1, W1);
    dequant_kernel_bf16<<<(unsigned)((H_ * H_) / 4 / 256), 256>>>(codes2, absmax2, W2b);
    dequant_kernel_bf16<<<(unsigned)((O_ * H_) / 4 / 256), 256>>>(codes3, absmax3, W3b);

    // layer 1: sequential-chain f32x2 (order noise cascades twice -> must stay), bf16 out
    sgemm_f32x2_l1<<<dim3(H_ / 128, B_ / 128), 256>>>(
        Xf, W1, bias1, H1b, (int)B_, (int)H_, (int)I_);
    // layer 2: HMMA bf16 (+relu), bf16 out
    gemm_hmma<true, false><<<dim3(H_ / 128, B_ / 128), 256>>>(
        H1b, W2b, bias2, H2b, (int)B_, (int)H_, (int)H_);
    // layer 3: HMMA bf16, f32 out (= upcast bf16)
    gemm_hmma<false, true><<<dim3(O_ / 128, B_ / 128), 256>>>(
        H2b, W3b, bias3, d_out, (int)B_, (int)O_, (int)H_);
}

// round 13
// speedup vs baseline: 1.0768x; 1.0768x over previous
#include <cuda_runtime.h>
#include <cuda_bf16.h>
#include <cstdint>

#define DI __device__ __forceinline__

// bitsandbytes FP4 codebook (sign = bit 3)
__constant__ float FP4_TAB[16] = {
     0.0f,  0.0052083333f,  0.6666667f,  1.0f,  0.3333333f,  0.5f,  0.1666667f,  0.25f,
    -0.0f, -0.0052083333f, -0.6666667f, -1.0f, -0.3333333f, -0.5f, -0.1666667f, -0.25f};

#define B_ 16384L
#define I_ 2048L
#define H_ 4096L
#define O_ 2048L

// scratch (alloc-free rule: __device__ globals)
__device__ float g_Xf[B_ * I_];           // exact bf16 values in f32 (layer-1 inputs)
__device__ float g_W1f[H_ * I_];
__device__ __nv_bfloat16 g_H1b[B_ * H_];  // layer-1 output, bf16 (exact)
__device__ __nv_bfloat16 g_W2b[H_ * H_];  // layer-2 weights, bf16
__device__ __nv_bfloat16 g_H2b[B_ * H_];  // layer-2 output, bf16
__device__ __nv_bfloat16 g_W3b[O_ * H_];  // layer-3 weights, bf16

DI float bf16v(float x) { return __bfloat162float(__float2bfloat16(x)); }

// packed dual-FP32 FMA (Blackwell FFMA2): per-lane IEEE RN fma.
DI void fma2(uint64_t& d, uint64_t a, uint64_t b) {
    asm("fma.rn.f32x2 %0, %1, %2, %3;" : "=l"(d) : "l"(a), "l"(b), "l"(d));
}
DI uint64_t pack2(float lo, float hi) {
    uint64_t r;
    asm("mov.b64 %0, {%1, %2};" : "=l"(r) : "f"(lo), "f"(hi));
    return r;
}
DI void unpack2(float& lo, float& hi, uint64_t v) {
    asm("mov.b64 {%0, %1}, %2;" : "=f"(lo), "=f"(hi) : "l"(v));
}

DI uint32_t s2u(const void* p) { return (uint32_t)__cvta_generic_to_shared(p); }
DI void cp16(uint32_t s, const void* g) {
    asm volatile("cp.async.cg.shared.global [%0], [%1], 16;\n" :: "r"(s), "l"(g) : "memory");
}
DI void cp_commit() { asm volatile("cp.async.commit_group;\n" ::: "memory"); }
template <int N>
DI void cp_wait() { asm volatile("cp.async.wait_group %0;\n" :: "n"(N) : "memory"); }
DI uint32_t lds32u(const __nv_bfloat16* p) { return *reinterpret_cast<const uint32_t*>(p); }
DI void mma16816(float* c, const uint32_t* a, const uint32_t* b) {
    asm volatile(
        "mma.sync.aligned.m16n8k16.row.col.f32.bf16.bf16.f32 "
        "{%0,%1,%2,%3}, {%4,%5,%6,%7}, {%8,%9}, {%0,%1,%2,%3};\n"
        : "+f"(c[0]), "+f"(c[1]), "+f"(c[2]), "+f"(c[3])
        : "r"(a[0]), "r"(a[1]), "r"(a[2]), "r"(a[3]), "r"(b[0]), "r"(b[1]));
}

// ---------------------------------------------------------------------------
// Elementwise prep
// ---------------------------------------------------------------------------

__global__ void cast_kernel(const float* __restrict__ x, float* __restrict__ y) {
    long i4 = blockIdx.x * (long)blockDim.x + threadIdx.x;
    float4 v = reinterpret_cast<const float4*>(x)[i4];
    float4 o;
    o.x = bf16v(v.x); o.y = bf16v(v.y); o.z = bf16v(v.z); o.w = bf16v(v.w);
    reinterpret_cast<float4*>(y)[i4] = o;
}

__global__ void dequant_kernel_f32(const int* __restrict__ codes,
                                   const float* __restrict__ absmax,
                                   float* __restrict__ w) {
    long i4 = blockIdx.x * (long)blockDim.x + threadIdx.x;
    int4 c = reinterpret_cast<const int4*>(codes)[i4];
    float am = __ldg(&absmax[(i4 * 4) >> 6]);
    float4 o;
    o.x = bf16v(FP4_TAB[c.x & 15] * am);
    o.y = bf16v(FP4_TAB[c.y & 15] * am);
    o.z = bf16v(FP4_TAB[c.z & 15] * am);
    o.w = bf16v(FP4_TAB[c.w & 15] * am);
    reinterpret_cast<float4*>(w)[i4] = o;
}

__global__ void dequant_kernel_bf16(const int* __restrict__ codes,
                                    const float* __restrict__ absmax,
                                    __nv_bfloat16* __restrict__ w) {
    long i4 = blockIdx.x * (long)blockDim.x + threadIdx.x;
    int4 c = reinterpret_cast<const int4*>(codes)[i4];
    float am = __ldg(&absmax[(i4 * 4) >> 6]);
    __nv_bfloat162 p0 = __floats2bfloat162_rn(FP4_TAB[c.x & 15] * am, FP4_TAB[c.y & 15] * am);
    __nv_bfloat162 p1 = __floats2bfloat162_rn(FP4_TAB[c.z & 15] * am, FP4_TAB[c.w & 15] * am);
    reinterpret_cast<__nv_bfloat162*>(w)[i4 * 2 + 0] = p0;
    reinterpret_cast<__nv_bfloat162*>(w)[i4 * 2 + 1] = p1;
}

// ---------------------------------------------------------------------------
// Layer 1: order-exact SGEMM on the FFMA2 pipe. A stored DUPLICATED in smem
// (k-row-major, chunk q*8+lr at word 32q+4lr within the warp half): mainloop
// = 32 FFMA2 + 4 LDS.128 (A) + 2 LDS.128 (B) per warp-k, zero pack-MOVs,
// reads conflict-free. Staging assignment PERMUTED so dup-stores hit all 16
// even bank-pairs per warp (2-transaction minimum for STS.64 = conflict-free).
// Per-element math bit-identical to R8/R10/R11 (sequential IEEE-FMA chain,
// ascending k).
// ---------------------------------------------------------------------------

__global__ void __launch_bounds__(256)
sgemm_f32x2_l1(const float* __restrict__ A,   // [M,K] f32 (bf16 values)
               const float* __restrict__ W,   // [N,K] f32 (bf16 values)
               const float* __restrict__ bias,
               __nv_bfloat16* __restrict__ C,
               int M, int N, int K) {
    constexpr int BM = 128, BN = 128, BK = 16;
    constexpr int LWA = 264;   // floats per k-row of A-dup (256 used + pad)
    constexpr int LWB = 132;
    __shared__ __align__(16) float sA[BK][LWA];
    __shared__ __align__(16) float sB[BK][LWB];

    const int tid  = threadIdx.x;
    const int lane = tid & 31;
    const int warp = tid >> 5;
    const int wm = (warp & 1) * 64;
    const int wn = (warp >> 1) * 32;
    const int lr = lane >> 2;
    const int lc = lane & 3;
    const int m0 = blockIdx.y * BM;
    const int n0 = blockIdx.x * BN;

    // --- staging assignment (permuted for conflict-free dup stores) ---
    // lane l of warp w stages A/W row sr, k-half sc. Constructed so that the
    // warp's 32 lanes cover lr_s = 0..7 and sub = 0..1 (16 even bank-pairs):
    const int sc     = (lane >> 4) * 8;       // 0 or 8
    const int half_s = warp >> 2;             // 0/1 (row half)
    const int qs     = warp & 3;              // chunk q
    const int lrs    = lane & 7;
    const int subs   = (lane >> 3) & 1;
    const int sr     = half_s * 64 + lrs * 8 + qs * 2 + subs;       // 0..127
    const int aoff   = half_s * 128 + qs * 32 + lrs * 4 + subs * 2; // word in k-row

    const float* gA = A + (size_t)(m0 + sr) * K + sc;
    const float* gW = W + (size_t)(n0 + sr) * K + sc;

    uint64_t acc[8][4];
#pragma unroll
    for (int i = 0; i < 8; i++)
#pragma unroll
        for (int j = 0; j < 4; j++) acc[i][j] = 0ull;

    float ra[8], rb[8];
    auto gload = [&]() {
        *reinterpret_cast<float4*>(ra)     = *reinterpret_cast<const float4*>(gA);
        *reinterpret_cast<float4*>(ra + 4) = *reinterpret_cast<const float4*>(gA + 4);
        *reinterpret_cast<float4*>(rb)     = *reinterpret_cast<const float4*>(gW);
        *reinterpret_cast<float4*>(rb + 4) = *reinterpret_cast<const float4*>(gW + 4);
    };
    auto sstore = [&]() {
#pragma unroll
        for (int t = 0; t < 8; t++) {
            *reinterpret_cast<uint64_t*>(&sA[sc + t][aoff]) = pack2(ra[t], ra[t]);
            sB[sc + t][sr] = rb[t];
        }
    };

    const int KT = K / BK;
    gload();
    for (int kt = 0; kt < KT; ++kt) {
        sstore();
        __syncthreads();
        if (kt + 1 < KT) { gA += BK; gW += BK; gload(); }

        const int abase = wm * 2 + lr * 4;   // word offset of lane's chunk q=0
#pragma unroll
        for (int k = 0; k < BK; k++) {       // ascending k — preserves chain order
            const float* ab = &sA[k][abase];
            uint64_t ad[8];
            *reinterpret_cast<ulonglong2*>(&ad[0]) = *reinterpret_cast<const ulonglong2*>(ab);
            *reinterpret_cast<ulonglong2*>(&ad[2]) = *reinterpret_cast<const ulonglong2*>(ab + 32);
            *reinterpret_cast<ulonglong2*>(&ad[4]) = *reinterpret_cast<const ulonglong2*>(ab + 64);
            *reinterpret_cast<ulonglong2*>(&ad[6]) = *reinterpret_cast<const ulonglong2*>(ab + 96);
            uint64_t bp[4];
            const uint64_t* bq = reinterpret_cast<const uint64_t*>(&sB[k][wn + lc * 8]);
            bp[0] = bq[0]; bp[1] = bq[1]; bp[2] = bq[2]; bp[3] = bq[3];
#pragma unroll
            for (int i = 0; i < 8; i++)
#pragma unroll
                for (int j = 0; j < 4; j++)
                    fma2(acc[i][j], ad[i], bp[j]);
        }
        __syncthreads();
    }

    // Epilogue — reference rounding: bf16(dot), + bf16(bias), bf16 round, relu.
    float bb[8];
#pragma unroll
    for (int j = 0; j < 8; j++) bb[j] = bf16v(bias[n0 + wn + lc * 8 + j]);

#pragma unroll
    for (int i = 0; i < 8; i++) {
        const int row = m0 + wm + lr * 8 + i;
        __nv_bfloat16* cp = C + (size_t)row * N + n0 + wn + lc * 8;
#pragma unroll
        for (int j = 0; j < 4; j++) {
            float v0, v1;
            unpack2(v0, v1, acc[i][j]);
            v0 = fmaxf(bf16v(bf16v(v0) + bb[2 * j]), 0.f);
            v1 = fmaxf(bf16v(bf16v(v1) + bb[2 * j + 1]), 0.f);
            reinterpret_cast<__nv_bfloat162*>(cp)[j] = __floats2bfloat162_rn(v0, v1);
        }
    }
}

// ---------------------------------------------------------------------------
// Layers 2-3: HMMA bf16 GEMM — EXACT R11 revert (BK=32, 2-stage, proven).
// ---------------------------------------------------------------------------

template <bool RELU, bool OUT_F32>
__global__ void __launch_bounds__(256)
gemm_hmma(const __nv_bfloat16* __restrict__ A,
          const __nv_bfloat16* __restrict__ W,
          const float* __restrict__ bias,
          void* __restrict__ Cv,
          int M, int N, int K) {
    constexpr int BM = 128, BN = 128, BK = 32;
    constexpr int LDS = BK + 8;

    __shared__ __align__(16) __nv_bfloat16 sA[2][BM * LDS];
    __shared__ __align__(16) __nv_bfloat16 sB[2][BN * LDS];

    const int tid = threadIdx.x;
    const int lane = tid & 31;
    const int warp = tid >> 5;
    const int wm = (warp & 1) * 64;
    const int wn = (warp >> 1) * 32;
    const int m0 = blockIdx.y * BM;
    const int n0 = blockIdx.x * BN;

    const int gid = lane >> 2;
    const int tg  = lane & 3;
    const int kfr = tg * 2;

    const int r_ld = tid >> 2;
    const int c_ld = (tid & 3) * 8;

    float acc[4][4][4];
#pragma unroll
    for (int i = 0; i < 4; i++)
#pragma unroll
        for (int j = 0; j < 4; j++)
#pragma unroll
            for (int q = 0; q < 4; q++) acc[i][j][q] = 0.f;

    auto load_stage = [&](int s, int kt) {
        const int k0 = kt * BK;
        const __nv_bfloat16* gA = A + (size_t)(m0 + r_ld) * K + k0 + c_ld;
        const __nv_bfloat16* gB = W + (size_t)(n0 + r_ld) * K + k0 + c_ld;
        cp16(s2u(&sA[s][r_ld * LDS + c_ld]), gA);
        cp16(s2u(&sB[s][r_ld * LDS + c_ld]), gB);
        cp16(s2u(&sA[s][(r_ld + 64) * LDS + c_ld]), gA + (size_t)64 * K);
        cp16(s2u(&sB[s][(r_ld + 64) * LDS + c_ld]), gB + (size_t)64 * K);
        cp_commit();
    };

    auto compute_stage = [&](int s) {
        const __nv_bfloat16* pA = sA[s];
        const __nv_bfloat16* pB = sB[s];
#pragma unroll
        for (int ks = 0; ks < 2; ks++) {
            const int kk = ks * 16;
            uint32_t a[4][4], b[4][2];
#pragma unroll
            for (int mt = 0; mt < 4; mt++) {
                const int r = wm + mt * 16 + gid;
                a[mt][0] = lds32u(&pA[(r    ) * LDS + kk + kfr    ]);
                a[mt][1] = lds32u(&pA[(r + 8) * LDS + kk + kfr    ]);
                a[mt][2] = lds32u(&pA[(r    ) * LDS + kk + kfr + 8]);
                a[mt][3] = lds32u(&pA[(r + 8) * LDS + kk + kfr + 8]);
            }
#pragma unroll
            for (int nt = 0; nt < 4; nt++) {
                const int n = wn + nt * 8 + gid;
                b[nt][0] = lds32u(&pB[n * LDS + kk + kfr    ]);
                b[nt][1] = lds32u(&pB[n * LDS + kk + kfr + 8]);
            }
#pragma unroll
            for (int mt = 0; mt < 4; mt++)
#pragma unroll
                for (int nt = 0; nt < 4; nt++)
                    mma16816(acc[mt][nt], a[mt], b[nt]);
        }
    };

    const int KT = K / BK;
    load_stage(0, 0);
    for (int kt = 0; kt < KT; ++kt) {
        if (kt + 1 < KT) {
            load_stage((kt + 1) & 1, kt + 1);
            cp_wait<1>();
        } else {
            cp_wait<0>();
        }
        __syncthreads();
        compute_stage(kt & 1);
        __syncthreads();
    }

    // Epilogue — reference rounding: bf16(dot) + bf16(bias) -> bf16 (+relu).
    __nv_bfloat16* Cb = (__nv_bfloat16*)Cv;
    float* Cf = (float*)Cv;
#pragma unroll
    for (int mt = 0; mt < 4; mt++) {
        const int rr = m0 + wm + mt * 16 + gid;
#pragma unroll
        for (int nt = 0; nt < 4; nt++) {
            const int cc = n0 + wn + nt * 8 + tg * 2;
            const float b0 = bf16v(bias[cc]);
            const float b1 = bf16v(bias[cc + 1]);
            const float* cr = acc[mt][nt];

            float v0 = bf16v(bf16v(cr[0]) + b0);
            float v1 = bf16v(bf16v(cr[1]) + b1);
            float v2 = bf16v(bf16v(cr[2]) + b0);
            float v3 = bf16v(bf16v(cr[3]) + b1);
            if (RELU) {
                v0 = fmaxf(v0, 0.f); v1 = fmaxf(v1, 0.f);
                v2 = fmaxf(v2, 0.f); v3 = fmaxf(v3, 0.f);
            }
            if (OUT_F32) {
                *reinterpret_cast<float2*>(&Cf[(size_t)rr * N + cc]) = make_float2(v0, v1);
                *reinterpret_cast<float2*>(&Cf[(size_t)(rr + 8) * N + cc]) = make_float2(v2, v3);
            } else {
                *reinterpret_cast<__nv_bfloat162*>(&Cb[(size_t)rr * N + cc]) =
                    __floats2bfloat162_rn(v0, v1);
                *reinterpret_cast<__nv_bfloat162*>(&Cb[(size_t)(rr + 8) * N + cc]) =
                    __floats2bfloat162_rn(v2, v3);
            }
        }
    }
}

// ---------------------------------------------------------------------------

extern "C" void kernel_launch(void* const* d_in, const int* in_sizes, int n_in,
                              void* d_out, int out_size) {
    // Resolve inputs by element count (robust to metadata ordering).
    const float* x = nullptr;
    const int *codes1 = nullptr, *codes2 = nullptr, *codes3 = nullptr;
    const float *absmax1 = nullptr, *absmax2 = nullptr, *absmax3 = nullptr;
    const float *bias1 = nullptr, *bias2 = nullptr, *bias3 = nullptr;

    for (int i = 0; i < n_in; i++) {
        const long sz = in_sizes[i];
        const void* p = d_in[i];
        if (sz == B_ * I_) x = (const float*)p;
        else if (sz == H_ * H_) codes2 = (const int*)p;
        else if (sz == H_ * I_) { if (!codes1) codes1 = (const int*)p; else codes3 = (const int*)p; }
        else if (sz == (H_ * H_) / 64) absmax2 = (const float*)p;
        else if (sz == (H_ * I_) / 64) { if (!absmax1) absmax1 = (const float*)p; else absmax3 = (const float*)p; }
        else if (sz == H_) { if (!bias1) bias1 = (const float*)p; else bias2 = (const float*)p; }
        else if (sz == O_) bias3 = (const float*)p;
    }

    float *Xf, *W1;
    __nv_bfloat16 *H1b, *W2b, *H2b, *W3b;
    cudaGetSymbolAddress((void**)&Xf, g_Xf);
    cudaGetSymbolAddress((void**)&W1, g_W1f);
    cudaGetSymbolAddress((void**)&H1b, g_H1b);
    cudaGetSymbolAddress((void**)&W2b, g_W2b);
    cudaGetSymbolAddress((void**)&H2b, g_H2b);
    cudaGetSymbolAddress((void**)&W3b, g_W3b);

    // elementwise prep
    cast_kernel<<<(unsigned)((B_ * I_) / 4 / 256), 256>>>(x, Xf);
    dequant_kernel_f32<<<(unsigned)((H_ * I_) / 4 / 256), 256>>>(codes1, absmax1, W1);
    dequant_kernel_bf16<<<(unsigned)((H_ * H_) / 4 / 256), 256>>>(codes2, absmax2, W2b);
    dequant_kernel_bf16<<<(unsigned)((O_ * H_) / 4 / 256), 256>>>(codes3, absmax3, W3b);

    // layer 1: sequential-chain f32x2 (order noise cascades twice -> must stay), bf16 out
    sgemm_f32x2_l1<<<dim3(H_ / 128, B_ / 128), 256>>>(
        Xf, W1, bias1, H1b, (int)B_, (int)H_, (int)I_);
    // layer 2: HMMA bf16 (+relu), bf16 out
    gemm_hmma<true, false><<<dim3(H_ / 128, B_ / 128), 256>>>(
        H1b, W2b, bias2, H2b, (int)B_, (int)H_, (int)H_);
    // layer 3: HMMA bf16, f32 out (= upcast bf16)
    gemm_hmma<false, true><<<dim3(O_ / 128, B_ / 128), 256>>>(
        H2b, W3b, bias3, d_out, (int)B_, (int)O_, (int)H_);
}

// round 14
// speedup vs baseline: 1.3731x; 1.2751x over previous
#include <cuda_runtime.h>
#include <cuda_bf16.h>
#include <cstdint>

#define DI __device__ __forceinline__

// bitsandbytes FP4 codebook (sign = bit 3)
__constant__ float FP4_TAB[16] = {
     0.0f,  0.0052083333f,  0.6666667f,  1.0f,  0.3333333f,  0.5f,  0.1666667f,  0.25f,
    -0.0f, -0.0052083333f, -0.6666667f, -1.0f, -0.3333333f, -0.5f, -0.1666667f, -0.25f};

#define B_ 16384L
#define I_ 2048L
#define H_ 4096L
#define O_ 2048L

// scratch (alloc-free rule: __device__ globals)
__device__ float g_Xf[B_ * I_];           // exact bf16 values in f32 (layer-1 inputs)
__device__ float g_W1f[H_ * I_];
__device__ __nv_bfloat16 g_H1b[B_ * H_];  // layer-1 output, bf16 (exact)
__device__ __nv_bfloat16 g_W2b[H_ * H_];  // layer-2 weights, bf16
__device__ __nv_bfloat16 g_H2b[B_ * H_];  // layer-2 output, bf16
__device__ __nv_bfloat16 g_W3b[O_ * H_];  // layer-3 weights, bf16

DI float bf16v(float x) { return __bfloat162float(__float2bfloat16(x)); }

// packed dual-FP32 FMA (Blackwell FFMA2): per-lane IEEE RN fma.
DI void fma2(uint64_t& d, uint64_t a, uint64_t b) {
    asm("fma.rn.f32x2 %0, %1, %2, %3;" : "=l"(d) : "l"(a), "l"(b), "l"(d));
}
DI uint64_t pack2(float lo, float hi) {
    uint64_t r;
    asm("mov.b64 %0, {%1, %2};" : "=l"(r) : "f"(lo), "f"(hi));
    return r;
}
DI void unpack2(float& lo, float& hi, uint64_t v) {
    asm("mov.b64 {%0, %1}, %2;" : "=f"(lo), "=f"(hi) : "l"(v));
}

DI uint32_t s2u(const void* p) { return (uint32_t)__cvta_generic_to_shared(p); }
DI void cp16(uint32_t s, const void* g) {
    asm volatile("cp.async.cg.shared.global [%0], [%1], 16;\n" :: "r"(s), "l"(g) : "memory");
}
DI void cp_commit() { asm volatile("cp.async.commit_group;\n" ::: "memory"); }
template <int N>
DI void cp_wait() { asm volatile("cp.async.wait_group %0;\n" :: "n"(N) : "memory"); }
DI void ldm_x4(uint32_t addr, uint32_t& r0, uint32_t& r1, uint32_t& r2, uint32_t& r3) {
    asm volatile("ldmatrix.sync.aligned.m8n8.x4.shared.b16 {%0,%1,%2,%3}, [%4];\n"
                 : "=r"(r0), "=r"(r1), "=r"(r2), "=r"(r3)
                 : "r"(addr));
}
DI void mma16816(float* c, const uint32_t* a, const uint32_t* b) {
    asm volatile(
        "mma.sync.aligned.m16n8k16.row.col.f32.bf16.bf16.f32 "
        "{%0,%1,%2,%3}, {%4,%5,%6,%7}, {%8,%9}, {%0,%1,%2,%3};\n"
        : "+f"(c[0]), "+f"(c[1]), "+f"(c[2]), "+f"(c[3])
        : "r"(a[0]), "r"(a[1]), "r"(a[2]), "r"(a[3]), "r"(b[0]), "r"(b[1]));
}

// ---------------------------------------------------------------------------
// Elementwise prep
// ---------------------------------------------------------------------------

__global__ void cast_kernel(const float* __restrict__ x, float* __restrict__ y) {
    long i4 = blockIdx.x * (long)blockDim.x + threadIdx.x;
    float4 v = reinterpret_cast<const float4*>(x)[i4];
    float4 o;
    o.x = bf16v(v.x); o.y = bf16v(v.y); o.z = bf16v(v.z); o.w = bf16v(v.w);
    reinterpret_cast<float4*>(y)[i4] = o;
}

__global__ void dequant_kernel_f32(const int* __restrict__ codes,
                                   const float* __restrict__ absmax,
                                   float* __restrict__ w) {
    long i4 = blockIdx.x * (long)blockDim.x + threadIdx.x;
    int4 c = reinterpret_cast<const int4*>(codes)[i4];
    float am = __ldg(&absmax[(i4 * 4) >> 6]);
    float4 o;
    o.x = bf16v(FP4_TAB[c.x & 15] * am);
    o.y = bf16v(FP4_TAB[c.y & 15] * am);
    o.z = bf16v(FP4_TAB[c.z & 15] * am);
    o.w = bf16v(FP4_TAB[c.w & 15] * am);
    reinterpret_cast<float4*>(w)[i4] = o;
}

__global__ void dequant_kernel_bf16(const int* __restrict__ codes,
                                    const float* __restrict__ absmax,
                                    __nv_bfloat16* __restrict__ w) {
    long i4 = blockIdx.x * (long)blockDim.x + threadIdx.x;
    int4 c = reinterpret_cast<const int4*>(codes)[i4];
    float am = __ldg(&absmax[(i4 * 4) >> 6]);
    __nv_bfloat162 p0 = __floats2bfloat162_rn(FP4_TAB[c.x & 15] * am, FP4_TAB[c.y & 15] * am);
    __nv_bfloat162 p1 = __floats2bfloat162_rn(FP4_TAB[c.z & 15] * am, FP4_TAB[c.w & 15] * am);
    reinterpret_cast<__nv_bfloat162*>(w)[i4 * 2 + 0] = p0;
    reinterpret_cast<__nv_bfloat162*>(w)[i4 * 2 + 1] = p1;
}

// ---------------------------------------------------------------------------
// Layer 1: order-exact SGEMM on the FFMA2 pipe — R11 version VERBATIM
// (proven: 8,373us total config). One sequential IEEE-FMA chain per output,
// ascending k.
// ---------------------------------------------------------------------------

__global__ void __launch_bounds__(256)
sgemm_f32x2_l1(const float* __restrict__ A,   // [M,K] f32 (bf16 values)
               const float* __restrict__ W,   // [N,K] f32 (bf16 values)
               const float* __restrict__ bias,
               __nv_bfloat16* __restrict__ C,
               int M, int N, int K) {
    constexpr int BM = 128, BN = 128, BK = 16, LW = 132;
    __shared__ __align__(16) float sA[BK][LW];
    __shared__ __align__(16) float sB[BK][LW];

    const int tid  = threadIdx.x;
    const int lane = tid & 31;
    const int warp = tid >> 5;
    const int wm = (warp & 1) * 64;
    const int wn = (warp >> 1) * 32;
    const int lr = lane >> 2;
    const int lc = lane & 3;
    const int m0 = blockIdx.y * BM;
    const int n0 = blockIdx.x * BN;

    const int sr = tid >> 1;
    const int sc = (tid & 1) * 8;

    const float* gA = A + (size_t)(m0 + sr) * K + sc;
    const float* gW = W + (size_t)(n0 + sr) * K + sc;

    uint64_t acc[8][4];
    const uint64_t z2 = pack2(0.f, 0.f);
#pragma unroll
    for (int i = 0; i < 8; i++)
#pragma unroll
        for (int j = 0; j < 4; j++) acc[i][j] = z2;

    float4 ra0 = *reinterpret_cast<const float4*>(gA);
    float4 ra1 = *reinterpret_cast<const float4*>(gA + 4);
    float4 rb0 = *reinterpret_cast<const float4*>(gW);
    float4 rb1 = *reinterpret_cast<const float4*>(gW + 4);

    const int KT = K / BK;
    for (int kt = 0; kt < KT; ++kt) {
        sA[sc + 0][sr] = ra0.x; sA[sc + 1][sr] = ra0.y;
        sA[sc + 2][sr] = ra0.z; sA[sc + 3][sr] = ra0.w;
        sA[sc + 4][sr] = ra1.x; sA[sc + 5][sr] = ra1.y;
        sA[sc + 6][sr] = ra1.z; sA[sc + 7][sr] = ra1.w;
        sB[sc + 0][sr] = rb0.x; sB[sc + 1][sr] = rb0.y;
        sB[sc + 2][sr] = rb0.z; sB[sc + 3][sr] = rb0.w;
        sB[sc + 4][sr] = rb1.x; sB[sc + 5][sr] = rb1.y;
        sB[sc + 6][sr] = rb1.z; sB[sc + 7][sr] = rb1.w;
        __syncthreads();

        if (kt + 1 < KT) {
            gA += BK; gW += BK;
            ra0 = *reinterpret_cast<const float4*>(gA);
            ra1 = *reinterpret_cast<const float4*>(gA + 4);
            rb0 = *reinterpret_cast<const float4*>(gW);
            rb1 = *reinterpret_cast<const float4*>(gW + 4);
        }

#pragma unroll
        for (int k = 0; k < BK; k++) {   // ascending k — preserves chain order
            float a[8];
            *reinterpret_cast<float4*>(a)     = *reinterpret_cast<const float4*>(&sA[k][wm + lr * 8]);
            *reinterpret_cast<float4*>(a + 4) = *reinterpret_cast<const float4*>(&sA[k][wm + lr * 8 + 4]);
            uint64_t bp[4];
            const uint64_t* bq = reinterpret_cast<const uint64_t*>(&sB[k][wn + lc * 8]);
            bp[0] = bq[0]; bp[1] = bq[1]; bp[2] = bq[2]; bp[3] = bq[3];
#pragma unroll
            for (int i = 0; i < 8; i++) {
                const uint64_t ad = pack2(a[i], a[i]);
#pragma unroll
                for (int j = 0; j < 4; j++)
                    fma2(acc[i][j], ad, bp[j]);
            }
        }
        __syncthreads();
    }

    float bb[8];
#pragma unroll
    for (int j = 0; j < 8; j++) bb[j] = bf16v(bias[n0 + wn + lc * 8 + j]);

#pragma unroll
    for (int i = 0; i < 8; i++) {
        const int row = m0 + wm + lr * 8 + i;
        __nv_bfloat16* cp = C + (size_t)row * N + n0 + wn + lc * 8;
#pragma unroll
        for (int j = 0; j < 4; j++) {
            float v0, v1;
            unpack2(v0, v1, acc[i][j]);
            v0 = fmaxf(bf16v(bf16v(v0) + bb[2 * j]), 0.f);
            v1 = fmaxf(bf16v(bf16v(v1) + bb[2 * j + 1]), 0.f);
            reinterpret_cast<__nv_bfloat162*>(cp)[j] = __floats2bfloat162_rn(v0, v1);
        }
    }
}

// ---------------------------------------------------------------------------
// Layers 2-3: HMMA bf16 GEMM (R11 structure: BK=32, 2-stage) with ldmatrix.x4
// fragment loads (bit-equivalent to explicit loads — verified R1 vs R2).
// ---------------------------------------------------------------------------

template <bool RELU, bool OUT_F32>
__global__ void __launch_bounds__(256)
gemm_hmma(const __nv_bfloat16* __restrict__ A,
          const __nv_bfloat16* __restrict__ W,
          const float* __restrict__ bias,
          void* __restrict__ Cv,
          int M, int N, int K) {
    constexpr int BM = 128, BN = 128, BK = 32;
    constexpr int LDS = BK + 8;

    __shared__ __align__(16) __nv_bfloat16 sA[2][BM * LDS];
    __shared__ __align__(16) __nv_bfloat16 sB[2][BN * LDS];

    const int tid = threadIdx.x;
    const int lane = tid & 31;
    const int warp = tid >> 5;
    const int wm = (warp & 1) * 64;
    const int wn = (warp >> 1) * 32;
    const int m0 = blockIdx.y * BM;
    const int n0 = blockIdx.x * BN;

    const int gid = lane >> 2;
    const int tg  = lane & 3;

    const int r_ld = tid >> 2;
    const int c_ld = (tid & 3) * 8;

    float acc[4][4][4];
#pragma unroll
    for (int i = 0; i < 4; i++)
#pragma unroll
        for (int j = 0; j < 4; j++)
#pragma unroll
            for (int q = 0; q < 4; q++) acc[i][j][q] = 0.f;

    auto load_stage = [&](int s, int kt) {
        const int k0 = kt * BK;
        const __nv_bfloat16* gA = A + (size_t)(m0 + r_ld) * K + k0 + c_ld;
        const __nv_bfloat16* gB = W + (size_t)(n0 + r_ld) * K + k0 + c_ld;
        cp16(s2u(&sA[s][r_ld * LDS + c_ld]), gA);
        cp16(s2u(&sB[s][r_ld * LDS + c_ld]), gB);
        cp16(s2u(&sA[s][(r_ld + 64) * LDS + c_ld]), gA + (size_t)64 * K);
        cp16(s2u(&sB[s][(r_ld + 64) * LDS + c_ld]), gB + (size_t)64 * K);
        cp_commit();
    };

    auto compute_stage = [&](int s) {
        const __nv_bfloat16* pA = sA[s];
        const __nv_bfloat16* pB = sB[s];
#pragma unroll
        for (int ks = 0; ks < 2; ks++) {
            const int kk = ks * 16;
            uint32_t a[4][4], b[4][2];
            // A fragments: 4 m16 tiles via ldmatrix.x4 (mapping verified R1≡R2)
            const int ar = lane & 15;
            const int ac = kk + ((lane >> 4) << 3);
#pragma unroll
            for (int mt = 0; mt < 4; mt++) {
                uint32_t addr = s2u(&pA[(wm + mt * 16 + ar) * LDS + ac]);
                ldm_x4(addr, a[mt][0], a[mt][1], a[mt][2], a[mt][3]);
            }
            // B fragments: 4 n8 tiles via 2 ldmatrix.x4
            const int br = (lane & 7) + ((lane >> 4) << 3);
            const int bc = kk + (((lane >> 3) & 1) << 3);
#pragma unroll
            for (int nt2 = 0; nt2 < 2; nt2++) {
                uint32_t addr = s2u(&pB[(wn + nt2 * 16 + br) * LDS + bc]);
                uint32_t r0, r1, r2, r3;
                ldm_x4(addr, r0, r1, r2, r3);
                b[nt2 * 2 + 0][0] = r0; b[nt2 * 2 + 0][1] = r1;
                b[nt2 * 2 + 1][0] = r2; b[nt2 * 2 + 1][1] = r3;
            }
#pragma unroll
            for (int mt = 0; mt < 4; mt++)
#pragma unroll
                for (int nt = 0; nt < 4; nt++)
                    mma16816(acc[mt][nt], a[mt], b[nt]);
        }
    };

    const int KT = K / BK;
    load_stage(0, 0);
    for (int kt = 0; kt < KT; ++kt) {
        if (kt + 1 < KT) {
            load_stage((kt + 1) & 1, kt + 1);
            cp_wait<1>();
        } else {
            cp_wait<0>();
        }
        __syncthreads();
        compute_stage(kt & 1);
        __syncthreads();
    }

    // Epilogue — reference rounding: bf16(dot) + bf16(bias) -> bf16 (+relu).
    __nv_bfloat16* Cb = (__nv_bfloat16*)Cv;
    float* Cf = (float*)Cv;
#pragma unroll
    for (int mt = 0; mt < 4; mt++) {
        const int rr = m0 + wm + mt * 16 + gid;
#pragma unroll
        for (int nt = 0; nt < 4; nt++) {
            const int cc = n0 + wn + nt * 8 + tg * 2;
            const float b0 = bf16v(bias[cc]);
            const float b1 = bf16v(bias[cc + 1]);
            const float* cr = acc[mt][nt];

            float v0 = bf16v(bf16v(cr[0]) + b0);
            float v1 = bf16v(bf16v(cr[1]) + b1);
            float v2 = bf16v(bf16v(cr[2]) + b0);
            float v3 = bf16v(bf16v(cr[3]) + b1);
            if (RELU) {
                v0 = fmaxf(v0, 0.f); v1 = fmaxf(v1, 0.f);
                v2 = fmaxf(v2, 0.f); v3 = fmaxf(v3, 0.f);
            }
            if (OUT_F32) {
                *reinterpret_cast<float2*>(&Cf[(size_t)rr * N + cc]) = make_float2(v0, v1);
                *reinterpret_cast<float2*>(&Cf[(size_t)(rr + 8) * N + cc]) = make_float2(v2, v3);
            } else {
                *reinterpret_cast<__nv_bfloat162*>(&Cb[(size_t)rr * N + cc]) =
                    __floats2bfloat162_rn(v0, v1);
                *reinterpret_cast<__nv_bfloat162*>(&Cb[(size_t)(rr + 8) * N + cc]) =
                    __floats2bfloat162_rn(v2, v3);
            }
        }
    }
}

// ---------------------------------------------------------------------------

extern "C" void kernel_launch(void* const* d_in, const int* in_sizes, int n_in,
                              void* d_out, int out_size) {
    // Resolve inputs by element count (robust to metadata ordering).
    const float* x = nullptr;
    const int *codes1 = nullptr, *codes2 = nullptr, *codes3 = nullptr;
    const float *absmax1 = nullptr, *absmax2 = nullptr, *absmax3 = nullptr;
    const float *bias1 = nullptr, *bias2 = nullptr, *bias3 = nullptr;

    for (int i = 0; i < n_in; i++) {
        const long sz = in_sizes[i];
        const void* p = d_in[i];
        if (sz == B_ * I_) x = (const float*)p;
        else if (sz == H_ * H_) codes2 = (const int*)p;
        else if (sz == H_ * I_) { if (!codes1) codes1 = (const int*)p; else codes3 = (const int*)p; }
        else if (sz == (H_ * H_) / 64) absmax2 = (const float*)p;
        else if (sz == (H_ * I_) / 64) { if (!absmax1) absmax1 = (const float*)p; else absmax3 = (const float*)p; }
        else if (sz == H_) { if (!bias1) bias1 = (const float*)p; else bias2 = (const float*)p; }
        else if (sz == O_) bias3 = (const float*)p;
    }

    float *Xf, *W1;
    __nv_bfloat16 *H1b, *W2b, *H2b, *W3b;
    cudaGetSymbolAddress((void**)&Xf, g_Xf);
    cudaGetSymbolAddress((void**)&W1, g_W1f);
    cudaGetSymbolAddress((void**)&H1b, g_H1b);
    cudaGetSymbolAddress((void**)&W2b, g_W2b);
    cudaGetSymbolAddress((void**)&H2b, g_H2b);
    cudaGetSymbolAddress((void**)&W3b, g_W3b);

    // elementwise prep
    cast_kernel<<<(unsigned)((B_ * I_) / 4 / 256), 256>>>(x, Xf);
    dequant_kernel_f32<<<(unsigned)((H_ * I_) / 4 / 256), 256>>>(codes1, absmax1, W1);
    dequant_kernel_bf16<<<(unsigned)((H_ * H_) / 4 / 256), 256>>>(codes2, absmax2, W2b);
    dequant_kernel_bf16<<<(unsigned)((O_ * H_) / 4 / 256), 256>>>(codes3, absmax3, W3b);

    // layer 1: sequential-chain f32x2 (order noise cascades twice -> must stay), bf16 out
    sgemm_f32x2_l1<<<dim3(H_ / 128, B_ / 128), 256>>>(
        Xf, W1, bias1, H1b, (int)B_, (int)H_, (int)I_);
    // layer 2: HMMA bf16 (+relu), bf16 out
    gemm_hmma<true, false><<<dim3(H_ / 128, B_ / 128), 256>>>(
        H1b, W2b, bias2, H2b, (int)B_, (int)H_, (int)H_);
    // layer 3: HMMA bf16, f32 out (= upcast bf16)
    gemm_hmma<false, true><<<dim3(O_ / 128, B_ / 128), 256>>>(
        H2b, W3b, bias3, d_out, (int)B_, (int)O_, (int)H_);
}